// round 12
// baseline (speedup 1.0000x reference)
#include <cuda_runtime.h>

#define BB 8
#define NN 2048
#define DD 1024
#define TT 4      // Taylor terms
#define CC 32     // chunks along N
#define LL 64     // NN / CC (rows per chunk)
#define DSPLIT 2
#define DHALF (DD / DSPLIT)   // 512 floats per CTA d-slice
#define NCTA (BB * CC * DSPLIT)   // 512 CTAs (power of 2, all co-resident @4/SM)
#define NTHR 256

// Scratch (static device arrays; no cudaMalloc allowed)
__device__ float g_k[BB * NN];
__device__ float g_q[BB * NN];
__device__ float g_part[(size_t)BB * CC * TT * DD];  // chunk vector moments -> prefixes
__device__ float g_smom [BB * CC * TT];              // chunk scalar moments
__device__ float g_spref[BB * CC * TT];              // exclusive scalar prefixes
__device__ unsigned int g_barcnt[3];                 // monotonic grid barriers

// Monotonic grid barrier: counter only grows; each launch adds exactly NCTA,
// so target = round_down(old, NCTA) + NCTA is correct across graph replays.
__device__ __forceinline__ void grid_bar(int which) {
    __syncthreads();
    if (threadIdx.x == 0) {
        __threadfence();                                  // publish our writes
        unsigned old = atomicAdd(&g_barcnt[which], 1u);
        unsigned target = (old & ~(unsigned)(NCTA - 1)) + NCTA;
        while ((int)(*(volatile unsigned*)&g_barcnt[which] - target) < 0) {}
        __threadfence();                                  // order spin before reads
    }
    __syncthreads();
}

__global__ __launch_bounds__(NTHR, 4) void k_all(const float* __restrict__ x,
                                                 const float* __restrict__ f,
                                                 const float* __restrict__ wk,
                                                 const float* __restrict__ wq,
                                                 float* __restrict__ out) {
    const int ds   = blockIdx.x;
    const int ch   = blockIdx.y;
    const int b    = blockIdx.z;
    const int tid  = threadIdx.x;
    const int wid  = tid >> 5;
    const int lane = tid & 31;
    const int bc   = b * CC + ch;                 // chunk id within batch space
    const int ctaL = ds + DSPLIT * (ch + CC * b); // linear CTA id

    __shared__ float sk[LL], sq[LL];

    // ---- Phase A: k,q projections. This CTA covers rows [ds*32, ds*32+32)
    //      of its chunk: 8 warps x 4 rows. Published via gmem for the peer CTA.
    const float4* wk4 = reinterpret_cast<const float4*>(wk);
    const float4* wq4 = reinterpret_cast<const float4*>(wq);
#pragma unroll
    for (int r = 0; r < 4; r++) {
        int rowl = ds * 32 + wid * 4 + r;
        int grow = b * NN + ch * LL + rowl;
        const float4* xr = reinterpret_cast<const float4*>(x) + (size_t)grow * (DD / 4);
        float dk = 0.f, dq = 0.f;
#pragma unroll
        for (int i = 0; i < 8; i++) {
            float4 v  = __ldcs(&xr[lane + 32 * i]);   // x never re-read
            float4 a  = wk4[lane + 32 * i];
            float4 bq = wq4[lane + 32 * i];
            dk += v.x * a.x + v.y * a.y + v.z * a.z + v.w * a.w;
            dq += v.x * bq.x + v.y * bq.y + v.z * bq.z + v.w * bq.w;
        }
#pragma unroll
        for (int off = 16; off > 0; off >>= 1) {
            dk += __shfl_down_sync(0xffffffffu, dk, off);
            dq += __shfl_down_sync(0xffffffffu, dq, off);
        }
        if (lane == 0) { g_k[grow] = dk; g_q[grow] = dq; }
    }

    grid_bar(0);

    // ---- load this chunk's 64 k,q into shared (written by this CTA + peer) ----
    if (tid < LL) {
        sk[tid] = __ldcg(&g_k[b * NN + ch * LL + tid]);
        sq[tid] = __ldcg(&g_q[b * NN + ch * LL + tid]);
    }
    __syncthreads();

    // ---- Phase B: chunk vector moments over this d-slice (float2/thread) ----
    const float2* fp = reinterpret_cast<const float2*>(
        f + (size_t)(b * NN + ch * LL) * DD + (size_t)ds * DHALF) + tid;

    {
        float2 S[TT];
#pragma unroll
        for (int t = 0; t < TT; t++) S[t] = make_float2(0.f, 0.f);
#pragma unroll 8
        for (int j = 0; j < LL; j++) {
            float2 fv = fp[(size_t)j * (DD / 2)];
            float kj = sk[j];
            S[0].x += fv.x; S[0].y += fv.y;
            float pk = kj;
#pragma unroll
            for (int t = 1; t < TT; t++) {
                S[t].x += pk * fv.x; S[t].y += pk * fv.y;
                pk *= kj;
            }
        }
        float2* gp = reinterpret_cast<float2*>(
            g_part + (size_t)(bc * TT) * DD + (size_t)ds * DHALF) + tid;
#pragma unroll
        for (int t = 0; t < TT; t++) gp[(size_t)t * (DD / 2)] = S[t];
    }

    if (ds == 0 && wid == 0) {   // scalar chunk moments over 64 rows (2/lane)
        float ka = sk[lane], kb = sk[lane + 32];
        float p1 = ka + kb;
        float p2 = ka * ka + kb * kb;
        float p3 = ka * ka * ka + kb * kb * kb;
#pragma unroll
        for (int off = 16; off > 0; off >>= 1) {
            p1 += __shfl_down_sync(0xffffffffu, p1, off);
            p2 += __shfl_down_sync(0xffffffffu, p2, off);
            p3 += __shfl_down_sync(0xffffffffu, p3, off);
        }
        if (lane == 0) {
            g_smom[bc * TT + 0] = (float)LL;
            g_smom[bc * TT + 1] = p1;
            g_smom[bc * TT + 2] = p2;
            g_smom[bc * TT + 3] = p3;
        }
    }

    grid_bar(1);

    // ---- Phase C: cross-chunk exclusive scans (R10 style: coalesced chains) ----
    if (ctaL < 128) {
        // vector chains: one per thread, idx in [0, BB*TT*DD) = 32768
        int idx = ctaL * NTHR + tid;
        int d   = idx % DD;
        int t   = (idx / DD) % TT;
        int bb  = idx / (DD * TT);
        size_t base   = (size_t)((bb * CC) * TT + t) * DD + d;
        size_t stride = (size_t)TT * DD;
        float run = 0.f;
#pragma unroll
        for (int half = 0; half < 2; half++) {
            float v[CC / 2];
#pragma unroll
            for (int c = 0; c < CC / 2; c++)
                v[c] = __ldcg(&g_part[base + (half * (CC / 2) + c) * stride]);
#pragma unroll
            for (int c = 0; c < CC / 2; c++) {
                float tmp = v[c];
                v[c] = run;
                run += tmp;
            }
#pragma unroll
            for (int c = 0; c < CC / 2; c++)
                g_part[base + (half * (CC / 2) + c) * stride] = v[c];
        }
    } else if (ctaL == 128 && tid < BB * TT) {
        // scalar chains: (b, t), 32 chunks, register-blocked
        int bb = tid / TT, t = tid % TT;
        float run = 0.f;
        float v[CC];
#pragma unroll
        for (int c = 0; c < CC; c++)
            v[c] = __ldcg(&g_smom[(bb * CC + c) * TT + t]);
#pragma unroll
        for (int c = 0; c < CC; c++) {
            float tmp = v[c];
            g_spref[(bb * CC + c) * TT + t] = run;
            run += tmp;
            (void)v[c]; (void)tmp;
        }
    }

    grid_bar(2);

    // ---- Phase D: resume scan within chunk, inline coefficients, output ----
    float2 S[TT];
    const float2* gp = reinterpret_cast<const float2*>(
        g_part + (size_t)(bc * TT) * DD + (size_t)ds * DHALF) + tid;
#pragma unroll
    for (int t = 0; t < TT; t++)
        S[t] = __ldcg(&gp[(size_t)t * (DD / 2)]);   // L2 (L1 may hold stale lines)

    float P0 = __ldcg(&g_spref[bc * TT + 0]);
    float P1 = __ldcg(&g_spref[bc * TT + 1]);
    float P2 = __ldcg(&g_spref[bc * TT + 2]);
    float P3 = __ldcg(&g_spref[bc * TT + 3]);

    float2* op = reinterpret_cast<float2*>(
        out + (size_t)(b * NN + ch * LL) * DD + (size_t)ds * DHALF) + tid;

#pragma unroll 8
    for (int j = 0; j < LL; j++) {
        float2 fv = fp[(size_t)j * (DD / 2)];       // re-read: L1/L2 hit from phase B
        float kj = sk[j];
        float k2 = kj * kj, k3 = k2 * kj;
        S[0].x += fv.x;      S[0].y += fv.y;
        S[1].x += kj * fv.x; S[1].y += kj * fv.y;
        S[2].x += k2 * fv.x; S[2].y += k2 * fv.y;
        S[3].x += k3 * fv.x; S[3].y += k3 * fv.y;
        P0 += 1.f; P1 += kj; P2 += k2; P3 += k3;

        float c   = sq[j] * 0.03125f;               // q_j / sqrt(D)
        float co1 = c;
        float co2 = c * c * 0.5f;
        float co3 = co2 * c * (1.f / 3.f);
        float Z  = P0 + co1 * P1 + co2 * P2 + co3 * P3;
        float iz = 1.f / Z;

        float2 acc;
        acc.x = (S[0].x + co1 * S[1].x + co2 * S[2].x + co3 * S[3].x) * iz;
        acc.y = (S[0].y + co1 * S[1].y + co2 * S[2].y + co3 * S[3].y) * iz;
        __stcs(&op[(size_t)j * (DD / 2)], acc);     // streaming: never re-read
    }
}

// ---------------------------------------------------------------------------
extern "C" void kernel_launch(void* const* d_in, const int* in_sizes, int n_in,
                              void* d_out, int out_size) {
    const float* x  = (const float*)d_in[0];
    const float* f  = (const float*)d_in[1];
    const float* wk = (const float*)d_in[2];
    const float* wq = (const float*)d_in[3];
    float* out = (float*)d_out;

    dim3 g(DSPLIT, CC, BB);                  // 512 CTAs x 256 thr — one wave
    k_all<<<g, NTHR>>>(x, f, wk, wq, out);
}

// round 13
// speedup vs baseline: 1.5200x; 1.5200x over previous
#include <cuda_runtime.h>

#define BB 8
#define NN 2048
#define DD 1024
#define TT 3     // Taylor terms (powers 0..2); typical |ck|~0.01, worst 0.17
#define CC 64    // chunks along N
#define LL 32    // NN / CC
#define NCTA (BB * CC)   // 512 CTAs, all co-resident (cap 592 @ 4/SM)
#define NTHR 256
#define NCHAINS (BB * TT * DD)          // 24576 vector chains
#define CBLK (NCHAINS / NTHR)           // 96 CTAs do the vector scan

// Scratch (static device arrays; no cudaMalloc allowed)
__device__ float g_part[(size_t)BB * CC * TT * DD];  // chunk vector moments -> prefixes
__device__ float g_smom [BB * CC * TT];              // chunk scalar moments
__device__ float g_spref[BB * CC * TT];              // exclusive scalar prefixes
__device__ unsigned int g_barcnt[2];                 // monotonic grid barriers

// Monotonic grid barrier: counter only grows; each launch adds exactly NCTA,
// so target = round_down(old, NCTA) + NCTA is correct across graph replays.
__device__ __forceinline__ void grid_bar(int which) {
    __syncthreads();
    if (threadIdx.x == 0) {
        __threadfence();                                  // publish our writes
        unsigned old = atomicAdd(&g_barcnt[which], 1u);
        unsigned target = (old & ~(unsigned)(NCTA - 1)) + NCTA;
        while ((int)(*(volatile unsigned*)&g_barcnt[which] - target) < 0) {}
        __threadfence();                                  // order spin before reads
    }
    __syncthreads();
}

__global__ __launch_bounds__(NTHR, 4) void k_all(const float* __restrict__ x,
                                                 const float* __restrict__ f,
                                                 const float* __restrict__ wk,
                                                 const float* __restrict__ wq,
                                                 float* __restrict__ out) {
    const int ch   = blockIdx.x;
    const int b    = blockIdx.y;
    const int tid  = threadIdx.x;
    const int wid  = tid >> 5;
    const int lane = tid & 31;
    const int cta  = b * CC + ch;

    __shared__ float sk[LL], sq[LL];

    // ---- Phase A: k,q projections for this CTA's 32 rows (8 warps x 4) ----
    const float4* wk4 = reinterpret_cast<const float4*>(wk);
    const float4* wq4 = reinterpret_cast<const float4*>(wq);
#pragma unroll
    for (int r = 0; r < 4; r++) {
        int rowl = wid * 4 + r;
        const float4* xr = reinterpret_cast<const float4*>(x) +
                           (size_t)(b * NN + ch * LL + rowl) * (DD / 4);
        float dk = 0.f, dq = 0.f;
#pragma unroll
        for (int i = 0; i < 8; i++) {
            float4 v  = __ldcs(&xr[lane + 32 * i]);   // x never re-read
            float4 a  = wk4[lane + 32 * i];
            float4 bq = wq4[lane + 32 * i];
            dk += v.x * a.x + v.y * a.y + v.z * a.z + v.w * a.w;
            dq += v.x * bq.x + v.y * bq.y + v.z * bq.z + v.w * bq.w;
        }
#pragma unroll
        for (int off = 16; off > 0; off >>= 1) {
            dk += __shfl_down_sync(0xffffffffu, dk, off);
            dq += __shfl_down_sync(0xffffffffu, dq, off);
        }
        if (lane == 0) { sk[rowl] = dk; sq[rowl] = dq; }
    }
    __syncthreads();

    // ---- Phase B: chunk vector moments (float4 per thread) + scalar moments ----
    const float4* fp = reinterpret_cast<const float4*>(
        f + (size_t)(b * NN + ch * LL) * DD) + tid;

    {
        float4 S[TT];
#pragma unroll
        for (int t = 0; t < TT; t++) S[t] = make_float4(0.f, 0.f, 0.f, 0.f);
#pragma unroll 8
        for (int j = 0; j < LL; j++) {
            float4 fv = fp[(size_t)j * (DD / 4)];
            float kj = sk[j];
            float k2 = kj * kj;
            S[0].x += fv.x;      S[0].y += fv.y;      S[0].z += fv.z;      S[0].w += fv.w;
            S[1].x += kj * fv.x; S[1].y += kj * fv.y; S[1].z += kj * fv.z; S[1].w += kj * fv.w;
            S[2].x += k2 * fv.x; S[2].y += k2 * fv.y; S[2].z += k2 * fv.z; S[2].w += k2 * fv.w;
        }
        float4* gp = reinterpret_cast<float4*>(
            g_part + (size_t)(cta * TT) * DD) + tid;
#pragma unroll
        for (int t = 0; t < TT; t++) gp[(size_t)t * (DD / 4)] = S[t];
    }

    if (wid == 0) {   // scalar chunk moments: warp-reduce k^t over 32 rows
        float kj = sk[lane];
        float p1 = kj, p2 = kj * kj;
#pragma unroll
        for (int off = 16; off > 0; off >>= 1) {
            p1 += __shfl_down_sync(0xffffffffu, p1, off);
            p2 += __shfl_down_sync(0xffffffffu, p2, off);
        }
        if (lane == 0) {
            g_smom[cta * TT + 0] = (float)LL;
            g_smom[cta * TT + 1] = p1;
            g_smom[cta * TT + 2] = p2;
        }
    }

    grid_bar(0);

    // ---- Phase C: cross-chunk exclusive scans ----
    if (cta < CBLK) {
        // vector chains: one per thread, idx in [0, NCHAINS)
        int idx = cta * NTHR + tid;
        int d   = idx % DD;
        int t   = (idx / DD) % TT;
        int bb  = idx / (DD * TT);
        size_t base   = (size_t)((bb * CC) * TT + t) * DD + d;
        size_t stride = (size_t)TT * DD;
        float run = 0.f;
#pragma unroll
        for (int half = 0; half < 2; half++) {
            float v[CC / 2];
#pragma unroll
            for (int c = 0; c < CC / 2; c++)
                v[c] = __ldcg(&g_part[base + (half * (CC / 2) + c) * stride]);
#pragma unroll
            for (int c = 0; c < CC / 2; c++) {
                float tmp = v[c];
                v[c] = run;
                run += tmp;
            }
#pragma unroll
            for (int c = 0; c < CC / 2; c++)
                g_part[base + (half * (CC / 2) + c) * stride] = v[c];
        }
    } else if (cta == CBLK && tid < BB * TT) {
        // scalar chains: (b, t), 64 chunks each, register-blocked
        int bb = tid / TT, t = tid % TT;
        float run = 0.f;
#pragma unroll
        for (int half = 0; half < 2; half++) {
            float v[CC / 2];
#pragma unroll
            for (int c = 0; c < CC / 2; c++)
                v[c] = __ldcg(&g_smom[(bb * CC + half * (CC / 2) + c) * TT + t]);
#pragma unroll
            for (int c = 0; c < CC / 2; c++) {
                float tmp = v[c];
                g_spref[(bb * CC + half * (CC / 2) + c) * TT + t] = run;
                run += tmp;
            }
        }
    }

    grid_bar(1);

    // ---- Phase D: resume scan within chunk, inline coefficients, output ----
    float4 S[TT];
    const float4* gp = reinterpret_cast<const float4*>(
        g_part + (size_t)(cta * TT) * DD) + tid;
#pragma unroll
    for (int t = 0; t < TT; t++)
        S[t] = __ldcg(&gp[(size_t)t * (DD / 4)]);   // L2 (L1 may hold stale lines)

    float P0 = __ldcg(&g_spref[cta * TT + 0]);
    float P1 = __ldcg(&g_spref[cta * TT + 1]);
    float P2 = __ldcg(&g_spref[cta * TT + 2]);

    float4* op = reinterpret_cast<float4*>(
        out + (size_t)(b * NN + ch * LL) * DD) + tid;

#pragma unroll 4
    for (int j = 0; j < LL; j++) {
        float4 fv = fp[(size_t)j * (DD / 4)];       // re-read: L2 hit from phase B
        float kj = sk[j];
        float k2 = kj * kj;
        S[0].x += fv.x;      S[0].y += fv.y;      S[0].z += fv.z;      S[0].w += fv.w;
        S[1].x += kj * fv.x; S[1].y += kj * fv.y; S[1].z += kj * fv.z; S[1].w += kj * fv.w;
        S[2].x += k2 * fv.x; S[2].y += k2 * fv.y; S[2].z += k2 * fv.z; S[2].w += k2 * fv.w;
        P0 += 1.f; P1 += kj; P2 += k2;

        float c   = sq[j] * 0.03125f;               // q_j / sqrt(D)
        float co1 = c;
        float co2 = c * c * 0.5f;
        float Z  = P0 + co1 * P1 + co2 * P2;
        float iz = 1.f / Z;

        float4 acc;
        acc.x = (S[0].x + co1 * S[1].x + co2 * S[2].x) * iz;
        acc.y = (S[0].y + co1 * S[1].y + co2 * S[2].y) * iz;
        acc.z = (S[0].z + co1 * S[1].z + co2 * S[2].z) * iz;
        acc.w = (S[0].w + co1 * S[1].w + co2 * S[2].w) * iz;
        __stcs(&op[(size_t)j * (DD / 4)], acc);     // streaming: never re-read
    }
}

// ---------------------------------------------------------------------------
extern "C" void kernel_launch(void* const* d_in, const int* in_sizes, int n_in,
                              void* d_out, int out_size) {
    const float* x  = (const float*)d_in[0];
    const float* f  = (const float*)d_in[1];
    const float* wk = (const float*)d_in[2];
    const float* wq = (const float*)d_in[3];
    float* out = (float*)d_out;

    dim3 g(CC, BB);                          // 512 CTAs x 256 thr — one wave
    k_all<<<g, NTHR>>>(x, f, wk, wq, out);
}